// round 2
// baseline (speedup 1.0000x reference)
#include <cuda_runtime.h>
#include <cuda_bf16.h>
#include <cstdint>

#define N_ATOMS 8192
#define M_BONDS 16
#define HID 256
#define NHEAD 8
#define HDIM 32

// ------------------------- static scratch (no allocs) -------------------------
static __device__ float g_attno[N_ATOMS * HID];                 // attention output
static __device__ float g_tmp  [N_ATOMS * HID];                 // pre-LN buffer
static __device__ float g_x1   [N_ATOMS * HID];                 // after LN1
static __device__ float g_xpart[N_ATOMS * HID];                 // x1 @ na_w1_top + b1
static __device__ float g_x2   [N_ATOMS * HID];                 // x1 + neighbor message
static __device__ float g_ff   [N_ATOMS * 4 * HID];             // relu(x2 @ ff_w1 + b1)
static __device__ float g_h    [(size_t)N_ATOMS * M_BONDS * HID]; // relu(cat @ na_w1 + b1)
static __device__ float g_scores[N_ATOMS * M_BONDS * NHEAD];    // neighbor scores
static __device__ __nv_bfloat16 g_q[(size_t)NHEAD * N_ATOMS * HDIM];
static __device__ __nv_bfloat16 g_k[(size_t)NHEAD * N_ATOMS * HDIM];
static __device__ __nv_bfloat16 g_v[(size_t)NHEAD * N_ATOMS * HDIM];

// ------------------------- mma helpers -------------------------
__device__ __forceinline__ uint32_t cvt_tf32(float x) {
    uint32_t r;
    asm("cvt.rna.tf32.f32 %0, %1;" : "=r"(r) : "f"(x));
    return r;
}

__device__ __forceinline__ void mma_tf32(float c[4], const uint32_t a[4], const uint32_t b[2]) {
    asm volatile(
        "mma.sync.aligned.m16n8k8.row.col.f32.tf32.tf32.f32 "
        "{%0,%1,%2,%3},{%4,%5,%6,%7},{%8,%9},{%0,%1,%2,%3};\n"
        : "+f"(c[0]), "+f"(c[1]), "+f"(c[2]), "+f"(c[3])
        : "r"(a[0]), "r"(a[1]), "r"(a[2]), "r"(a[3]), "r"(b[0]), "r"(b[1]));
}

__device__ __forceinline__ void mma_bf16(float c[4], const uint32_t a[4], const uint32_t b[2]) {
    asm volatile(
        "mma.sync.aligned.m16n8k16.row.col.f32.bf16.bf16.f32 "
        "{%0,%1,%2,%3},{%4,%5,%6,%7},{%8,%9},{%0,%1,%2,%3};\n"
        : "+f"(c[0]), "+f"(c[1]), "+f"(c[2]), "+f"(c[3])
        : "r"(a[0]), "r"(a[1]), "r"(a[2]), "r"(a[3]), "r"(b[0]), "r"(b[1]));
}

__device__ __forceinline__ uint32_t pack_bf16x2(float lo, float hi) {
    __nv_bfloat162 t = __floats2bfloat162_rn(lo, hi);
    return *reinterpret_cast<uint32_t*>(&t);
}

// ------------------------- generic tf32 GEMM -------------------------
// C[M,N] = A[M,K] @ B[K,N] (+bias) with per-mode epilogue.
// BM=128, BN=64, BK=16, 256 threads (8 warps), warp = 16-row strip x 64 cols.
// MODE 0: qkv -> scatter bf16 q/k/v head-major (q scaled by 1/sqrt(32))
// MODE 1: + bias + residual(extra) -> Cout            (out proj)
// MODE 2: + bias -> Cout                              (xpart)
// MODE 3: + bias, relu -> Cout                        (ffn1)
// MODE 4: + bias + residual(extra) -> Cout            (ffn2)
// MODE 5: + xpart[row/16] (bias folded there), relu -> Cout (neighbor part)
#define AS_STRIDE 17
#define BS_STRIDE 68

template <int MODE>
__global__ void __launch_bounds__(256)
gemm_tf32_kernel(const float* __restrict__ A, const float* __restrict__ B,
                 const float* __restrict__ bias, const float* __restrict__ extra,
                 float* __restrict__ Cout, int Mrows, int Ncols, int K) {
    __shared__ float As[128 * AS_STRIDE];
    __shared__ float Bs[16 * BS_STRIDE];

    const int bm = blockIdx.y * 128;
    const int bn = blockIdx.x * 64;
    const int tid = threadIdx.x;
    const int warp = tid >> 5;
    const int lane = tid & 31;
    const int g = lane >> 2;   // group id (row)
    const int tg = lane & 3;   // thread in group

    float acc[8][4];
#pragma unroll
    for (int t = 0; t < 8; t++)
#pragma unroll
        for (int i = 0; i < 4; i++) acc[t][i] = 0.f;

    const int wr = warp * 16;

    for (int k0 = 0; k0 < K; k0 += 16) {
        // load A tile 128x16
#pragma unroll
        for (int i = 0; i < 8; i++) {
            int e = tid + i * 256;
            int r = e >> 4, c = e & 15;
            As[r * AS_STRIDE + c] = A[(size_t)(bm + r) * K + k0 + c];
        }
        // load B tile 16x64
#pragma unroll
        for (int i = 0; i < 4; i++) {
            int e = tid + i * 256;
            int r = e >> 6, c = e & 63;
            Bs[r * BS_STRIDE + c] = B[(size_t)(k0 + r) * Ncols + bn + c];
        }
        __syncthreads();

#pragma unroll
        for (int s = 0; s < 2; s++) {
            uint32_t a[4];
            a[0] = cvt_tf32(As[(wr + g) * AS_STRIDE + s * 8 + tg]);
            a[1] = cvt_tf32(As[(wr + g + 8) * AS_STRIDE + s * 8 + tg]);
            a[2] = cvt_tf32(As[(wr + g) * AS_STRIDE + s * 8 + tg + 4]);
            a[3] = cvt_tf32(As[(wr + g + 8) * AS_STRIDE + s * 8 + tg + 4]);
#pragma unroll
            for (int t = 0; t < 8; t++) {
                uint32_t b[2];
                b[0] = cvt_tf32(Bs[(s * 8 + tg) * BS_STRIDE + t * 8 + g]);
                b[1] = cvt_tf32(Bs[(s * 8 + tg + 4) * BS_STRIDE + t * 8 + g]);
                mma_tf32(acc[t], a, b);
            }
        }
        __syncthreads();
    }

    // epilogue
#pragma unroll
    for (int t = 0; t < 8; t++) {
#pragma unroll
        for (int i = 0; i < 2; i++) {
            int row = bm + wr + g + i * 8;
#pragma unroll
            for (int j = 0; j < 2; j++) {
                int col = bn + t * 8 + tg * 2 + j;
                float v = acc[t][i * 2 + j];
                if (bias != nullptr) v += bias[col];
                if (MODE == 0) {
                    int part = col >> 8;
                    int head = (col & 255) >> 5;
                    int d = col & 31;
                    size_t idx = ((size_t)head * N_ATOMS + row) * HDIM + d;
                    if (part == 0)      g_q[idx] = __float2bfloat16(v * 0.17677669529663689f);
                    else if (part == 1) g_k[idx] = __float2bfloat16(v);
                    else                g_v[idx] = __float2bfloat16(v);
                } else if (MODE == 1 || MODE == 4) {
                    Cout[(size_t)row * Ncols + col] = v + extra[(size_t)row * Ncols + col];
                } else if (MODE == 2) {
                    Cout[(size_t)row * Ncols + col] = v;
                } else if (MODE == 3) {
                    Cout[(size_t)row * Ncols + col] = fmaxf(v, 0.f);
                } else { // MODE 5
                    v += extra[(size_t)(row >> 4) * HID + col];
                    Cout[(size_t)row * Ncols + col] = fmaxf(v, 0.f);
                }
            }
        }
    }
}

// ------------------------- flash attention (bf16 mma) -------------------------
// grid (128 q-tiles, 8 heads), 128 threads (4 warps), each warp 16 q-rows.
#define KS_STRIDE 40   // halves per K row (32 + pad)
#define VT_STRIDE 72   // halves per Vt row (64 + pad)

__global__ void __launch_bounds__(128)
flash_attn_kernel() {
    const int h = blockIdx.y;
    const int qt = blockIdx.x;
    const int warp = threadIdx.x >> 5;
    const int lane = threadIdx.x & 31;
    const int g = lane >> 2;
    const int tg = lane & 3;

    __shared__ __align__(16) __nv_bfloat16 Ks[64 * KS_STRIDE];
    __shared__ __align__(16) __nv_bfloat16 Vt[32 * VT_STRIDE];

    const int qrow = qt * 64 + warp * 16;

    // load Q fragments (rows within this head) into registers
    const uint32_t* qbase = reinterpret_cast<const uint32_t*>(g_q + (size_t)h * N_ATOMS * HDIM);
    uint32_t qf[2][4];
#pragma unroll
    for (int s = 0; s < 2; s++) {
        qf[s][0] = qbase[(qrow + g) * 16 + s * 8 + tg];
        qf[s][1] = qbase[(qrow + g + 8) * 16 + s * 8 + tg];
        qf[s][2] = qbase[(qrow + g) * 16 + s * 8 + tg + 4];
        qf[s][3] = qbase[(qrow + g + 8) * 16 + s * 8 + tg + 4];
    }

    float o[4][4];
#pragma unroll
    for (int t = 0; t < 4; t++)
#pragma unroll
        for (int i = 0; i < 4; i++) o[t][i] = 0.f;

    float m0 = -1e30f, m1 = -1e30f, l0 = 0.f, l1 = 0.f;

    const __nv_bfloat16* Kg = g_k + (size_t)h * N_ATOMS * HDIM;
    const __nv_bfloat16* Vg = g_v + (size_t)h * N_ATOMS * HDIM;

    for (int kt = 0; kt < N_ATOMS; kt += 64) {
        // load K tile 64x32 (row-major, padded)
        const uint32_t* Kw = reinterpret_cast<const uint32_t*>(Kg + (size_t)kt * HDIM);
#pragma unroll
        for (int i = 0; i < 8; i++) {
            int e = threadIdx.x + i * 128;
            int r = e >> 4, cw = e & 15;
            *reinterpret_cast<uint32_t*>(&Ks[r * KS_STRIDE + cw * 2]) = Kw[e];
        }
        // load V tile transposed: Vt[d][key]
        const uint32_t* Vw = reinterpret_cast<const uint32_t*>(Vg + (size_t)kt * HDIM);
#pragma unroll
        for (int i = 0; i < 8; i++) {
            int e = threadIdx.x + i * 128;
            int key = e >> 4, dw = e & 15;
            uint32_t w = Vw[e];
            __nv_bfloat162 pv = *reinterpret_cast<__nv_bfloat162*>(&w);
            Vt[(dw * 2) * VT_STRIDE + key] = pv.x;
            Vt[(dw * 2 + 1) * VT_STRIDE + key] = pv.y;
        }
        __syncthreads();

        // S = Q @ K^T   (16 x 64)
        float s[8][4];
#pragma unroll
        for (int t = 0; t < 8; t++)
#pragma unroll
            for (int i = 0; i < 4; i++) s[t][i] = 0.f;

#pragma unroll
        for (int sl = 0; sl < 2; sl++) {
#pragma unroll
            for (int t = 0; t < 8; t++) {
                uint32_t b[2];
                b[0] = *reinterpret_cast<const uint32_t*>(&Ks[(t * 8 + g) * KS_STRIDE + sl * 16 + tg * 2]);
                b[1] = *reinterpret_cast<const uint32_t*>(&Ks[(t * 8 + g) * KS_STRIDE + sl * 16 + 8 + tg * 2]);
                mma_bf16(s[t], qf[sl], b);
            }
        }

        // online softmax
        float mt0 = -1e30f, mt1 = -1e30f;
#pragma unroll
        for (int t = 0; t < 8; t++) {
            mt0 = fmaxf(mt0, fmaxf(s[t][0], s[t][1]));
            mt1 = fmaxf(mt1, fmaxf(s[t][2], s[t][3]));
        }
        mt0 = fmaxf(mt0, __shfl_xor_sync(0xffffffffu, mt0, 1));
        mt0 = fmaxf(mt0, __shfl_xor_sync(0xffffffffu, mt0, 2));
        mt1 = fmaxf(mt1, __shfl_xor_sync(0xffffffffu, mt1, 1));
        mt1 = fmaxf(mt1, __shfl_xor_sync(0xffffffffu, mt1, 2));

        float mn0 = fmaxf(m0, mt0);
        float mn1 = fmaxf(m1, mt1);
        float sc0 = __expf(m0 - mn0);
        float sc1 = __expf(m1 - mn1);

        float rs0 = 0.f, rs1 = 0.f;
        uint32_t p[4][4];
#pragma unroll
        for (int t2 = 0; t2 < 4; t2++) {
            float e00 = __expf(s[2 * t2][0] - mn0);
            float e01 = __expf(s[2 * t2][1] - mn0);
            float e02 = __expf(s[2 * t2][2] - mn1);
            float e03 = __expf(s[2 * t2][3] - mn1);
            float e10 = __expf(s[2 * t2 + 1][0] - mn0);
            float e11 = __expf(s[2 * t2 + 1][1] - mn0);
            float e12 = __expf(s[2 * t2 + 1][2] - mn1);
            float e13 = __expf(s[2 * t2 + 1][3] - mn1);
            rs0 += e00 + e01 + e10 + e11;
            rs1 += e02 + e03 + e12 + e13;
            p[t2][0] = pack_bf16x2(e00, e01);
            p[t2][1] = pack_bf16x2(e02, e03);
            p[t2][2] = pack_bf16x2(e10, e11);
            p[t2][3] = pack_bf16x2(e12, e13);
        }
        rs0 += __shfl_xor_sync(0xffffffffu, rs0, 1);
        rs0 += __shfl_xor_sync(0xffffffffu, rs0, 2);
        rs1 += __shfl_xor_sync(0xffffffffu, rs1, 1);
        rs1 += __shfl_xor_sync(0xffffffffu, rs1, 2);

        l0 = l0 * sc0 + rs0;
        l1 = l1 * sc1 + rs1;
        m0 = mn0;
        m1 = mn1;

#pragma unroll
        for (int t = 0; t < 4; t++) {
            o[t][0] *= sc0; o[t][1] *= sc0;
            o[t][2] *= sc1; o[t][3] *= sc1;
        }

        // O += P @ V
#pragma unroll
        for (int k2 = 0; k2 < 4; k2++) {
#pragma unroll
            for (int t = 0; t < 4; t++) {
                uint32_t b[2];
                b[0] = *reinterpret_cast<const uint32_t*>(&Vt[(t * 8 + g) * VT_STRIDE + k2 * 16 + tg * 2]);
                b[1] = *reinterpret_cast<const uint32_t*>(&Vt[(t * 8 + g) * VT_STRIDE + k2 * 16 + 8 + tg * 2]);
                mma_bf16(o[t], p[k2], b);
            }
        }
        __syncthreads();
    }

    const float il0 = 1.f / l0;
    const float il1 = 1.f / l1;
    const int r0 = qrow + g;
    const int r1 = qrow + g + 8;
#pragma unroll
    for (int t = 0; t < 4; t++) {
        int col = h * HDIM + t * 8 + tg * 2;
        g_attno[(size_t)r0 * HID + col]     = o[t][0] * il0;
        g_attno[(size_t)r0 * HID + col + 1] = o[t][1] * il0;
        g_attno[(size_t)r1 * HID + col]     = o[t][2] * il1;
        g_attno[(size_t)r1 * HID + col + 1] = o[t][3] * il1;
    }
}

// ------------------------- layer norm -------------------------
// one warp per row (256 cols, 8 per lane), 4 warps per block
__global__ void __launch_bounds__(128)
ln_kernel(const float* __restrict__ in, const float* __restrict__ scale,
          const float* __restrict__ bias, float* __restrict__ out) {
    const int warp = threadIdx.x >> 5;
    const int lane = threadIdx.x & 31;
    const int row = blockIdx.x * 4 + warp;
    const float* r = in + (size_t)row * HID;

    float v[8];
#pragma unroll
    for (int i = 0; i < 8; i++) v[i] = r[lane + i * 32];

    float s = 0.f;
#pragma unroll
    for (int i = 0; i < 8; i++) s += v[i];
#pragma unroll
    for (int o = 16; o > 0; o >>= 1) s += __shfl_xor_sync(0xffffffffu, s, o);
    const float mu = s * (1.f / HID);

    float q = 0.f;
#pragma unroll
    for (int i = 0; i < 8; i++) {
        float d = v[i] - mu;
        q += d * d;
    }
#pragma unroll
    for (int o = 16; o > 0; o >>= 1) q += __shfl_xor_sync(0xffffffffu, q, o);
    const float inv = rsqrtf(q * (1.f / HID) + 1e-5f);

#pragma unroll
    for (int i = 0; i < 8; i++) {
        int c = lane + i * 32;
        out[(size_t)row * HID + c] = (v[i] - mu) * inv * scale[c] + bias[c];
    }
}

// ------------------------- neighbor scores: h @ na_w2 + b2 -------------------------
// warp per row of h (131072 rows), w2 transposed in smem (conflict-free)
__global__ void __launch_bounds__(256)
scores_kernel(const float* __restrict__ w2, const float* __restrict__ b2) {
    __shared__ float w2t[NHEAD * HID]; // [j][c]
    for (int i = threadIdx.x; i < NHEAD * HID; i += 256)
        w2t[(i & 7) * HID + (i >> 3)] = w2[i];
    __syncthreads();

    const int warp = threadIdx.x >> 5;
    const int lane = threadIdx.x & 31;
    const size_t row = (size_t)blockIdx.x * 8 + warp;
    const float* hr = g_h + row * HID;

    float acc[NHEAD];
#pragma unroll
    for (int j = 0; j < NHEAD; j++) acc[j] = 0.f;

#pragma unroll
    for (int c = 0; c < 8; c++) {
        float hv = hr[c * 32 + lane];
#pragma unroll
        for (int j = 0; j < NHEAD; j++)
            acc[j] += hv * w2t[j * HID + c * 32 + lane];
    }
#pragma unroll
    for (int j = 0; j < NHEAD; j++) {
#pragma unroll
        for (int o = 16; o > 0; o >>= 1)
            acc[j] += __shfl_xor_sync(0xffffffffu, acc[j], o);
    }
    if (lane == 0) {
#pragma unroll
        for (int j = 0; j < NHEAD; j++)
            g_scores[row * NHEAD + j] = acc[j] + b2[j];
    }
}

// ------------------------- neighbor softmax + message + residual -------------------------
// one block (256 threads) per atom
__global__ void __launch_bounds__(256)
neighbor_msg_kernel(const float* __restrict__ neighbors, const float* __restrict__ edge) {
    const int n = blockIdx.x;
    const int tid = threadIdx.x;

    __shared__ float sc[M_BONDS][NHEAD];
    __shared__ float wn[M_BONDS][NHEAD];
    __shared__ float w[M_BONDS];

    if (tid < M_BONDS * NHEAD)
        sc[tid >> 3][tid & 7] = g_scores[(size_t)n * (M_BONDS * NHEAD) + tid];
    __syncthreads();

    if (tid < NHEAD) {
        float mx = -1e30f;
        for (int m = 0; m < M_BONDS; m++) mx = fmaxf(mx, sc[m][tid]);
        float s = 0.f;
        for (int m = 0; m < M_BONDS; m++) {
            float e = __expf(sc[m][tid] - mx);
            wn[m][tid] = e;
            s += e;
        }
        float inv = 1.f / s;
        for (int m = 0; m < M_BONDS; m++) wn[m][tid] *= inv;
    }
    __syncthreads();
    if (tid < M_BONDS) {
        float s = 0.f;
        for (int j = 0; j < NHEAD; j++) s += wn[tid][j];
        w[tid] = s * (1.f / NHEAD);
    }
    __syncthreads();

    const int d = tid;
    const size_t base = ((size_t)n * M_BONDS) * HID + d;
    float msg = 0.f;
#pragma unroll
    for (int m = 0; m < M_BONDS; m++)
        msg += neighbors[base + (size_t)m * HID] * edge[base + (size_t)m * HID] * w[m];
    g_x2[(size_t)n * HID + d] = g_x1[(size_t)n * HID + d] + msg;
}

// ------------------------- launch -------------------------
extern "C" void kernel_launch(void* const* d_in, const int* in_sizes, int n_in,
                              void* d_out, int out_size) {
    const float* x          = (const float*)d_in[0];
    const float* neighbors  = (const float*)d_in[1];
    const float* edge       = (const float*)d_in[2];
    const float* in_proj_w  = (const float*)d_in[3];
    const float* in_proj_b  = (const float*)d_in[4];
    const float* out_proj_w = (const float*)d_in[5];
    const float* out_proj_b = (const float*)d_in[6];
    const float* ln1_s      = (const float*)d_in[7];
    const float* ln1_b      = (const float*)d_in[8];
    const float* na_w1      = (const float*)d_in[9];
    const float* na_b1      = (const float*)d_in[10];
    const float* na_w2      = (const float*)d_in[11];
    const float* na_b2      = (const float*)d_in[12];
    const float* ff_w1      = (const float*)d_in[13];
    const float* ff_b1      = (const float*)d_in[14];
    const float* ff_w2      = (const float*)d_in[15];
    const float* ff_b2      = (const float*)d_in[16];
    const float* ln2_s      = (const float*)d_in[17];
    const float* ln2_b      = (const float*)d_in[18];
    float* out = (float*)d_out;

    float *attno, *tmp, *x1, *xpart, *x2, *ff, *hbuf;
    cudaGetSymbolAddress((void**)&attno, g_attno);
    cudaGetSymbolAddress((void**)&tmp,   g_tmp);
    cudaGetSymbolAddress((void**)&x1,    g_x1);
    cudaGetSymbolAddress((void**)&xpart, g_xpart);
    cudaGetSymbolAddress((void**)&x2,    g_x2);
    cudaGetSymbolAddress((void**)&ff,    g_ff);
    cudaGetSymbolAddress((void**)&hbuf,  g_h);

    // 1. qkv projection -> bf16 q/k/v (head-major), q pre-scaled
    gemm_tf32_kernel<0><<<dim3(768 / 64, N_ATOMS / 128), 256>>>(
        x, in_proj_w, in_proj_b, nullptr, nullptr, N_ATOMS, 768, HID);

    // 2. flash attention -> g_attno
    flash_attn_kernel<<<dim3(N_ATOMS / 64, NHEAD), 128>>>();

    // 3. out-proj + residual -> g_tmp
    gemm_tf32_kernel<1><<<dim3(HID / 64, N_ATOMS / 128), 256>>>(
        attno, out_proj_w, out_proj_b, x, tmp, N_ATOMS, HID, HID);

    // 4. LN1 -> g_x1
    ln_kernel<<<N_ATOMS / 4, 128>>>(tmp, ln1_s, ln1_b, x1);

    // 5. x-part of neighbor MLP: x1 @ na_w1[0:256] + na_b1 -> g_xpart
    gemm_tf32_kernel<2><<<dim3(HID / 64, N_ATOMS / 128), 256>>>(
        x1, na_w1, na_b1, nullptr, xpart, N_ATOMS, HID, HID);

    // 6. neighbor part: relu(neighbors @ na_w1[256:512] + xpart) -> g_h
    gemm_tf32_kernel<5><<<dim3(HID / 64, (N_ATOMS * M_BONDS) / 128), 256>>>(
        neighbors, na_w1 + 256 * HID, nullptr, xpart, hbuf,
        N_ATOMS * M_BONDS, HID, HID);

    // 7. scores = h @ na_w2 + b2
    scores_kernel<<<(N_ATOMS * M_BONDS) / 8, 256>>>(na_w2, na_b2);

    // 8. softmax over bonds, mean over heads, message, residual -> g_x2
    neighbor_msg_kernel<<<N_ATOMS, 256>>>(neighbors, edge);

    // 9. FFN layer 1: relu(x2 @ ff_w1 + b1) -> g_ff
    gemm_tf32_kernel<3><<<dim3(1024 / 64, N_ATOMS / 128), 256>>>(
        x2, ff_w1, ff_b1, nullptr, ff, N_ATOMS, 1024, HID);

    // 10. FFN layer 2 + residual -> g_tmp
    gemm_tf32_kernel<4><<<dim3(HID / 64, N_ATOMS / 128), 256>>>(
        ff, ff_w2, ff_b2, x2, tmp, N_ATOMS, HID, 1024);

    // 11. LN2 -> out
    ln_kernel<<<N_ATOMS / 4, 128>>>(tmp, ln2_s, ln2_b, out);
}

// round 5
// speedup vs baseline: 1.6287x; 1.6287x over previous
#include <cuda_runtime.h>
#include <cuda_bf16.h>
#include <cstdint>

#define N_ATOMS 8192
#define M_BONDS 16
#define HID 256
#define NHEAD 8
#define HDIM 32

// ------------------------- static scratch (no allocs) -------------------------
static __device__ float g_attno[N_ATOMS * HID];
static __device__ float g_tmp  [N_ATOMS * HID];
static __device__ float g_x1   [N_ATOMS * HID];
static __device__ float g_xpart[N_ATOMS * HID];
static __device__ float g_x2   [N_ATOMS * HID];
static __device__ float g_ff   [N_ATOMS * 4 * HID];
static __device__ float g_scores[N_ATOMS * M_BONDS * NHEAD];
static __device__ __nv_bfloat16 g_q[(size_t)NHEAD * N_ATOMS * HDIM];
static __device__ __nv_bfloat16 g_k[(size_t)NHEAD * N_ATOMS * HDIM];
static __device__ __nv_bfloat16 g_v[(size_t)NHEAD * N_ATOMS * HDIM];

// ------------------------- helpers -------------------------
__device__ __forceinline__ uint32_t cvt_tf32(float x) {
    uint32_t r;
    asm("cvt.rna.tf32.f32 %0, %1;" : "=r"(r) : "f"(x));
    return r;
}

__device__ __forceinline__ void mma_tf32(float c[4], const uint32_t a[4], const uint32_t b[2]) {
    asm volatile(
        "mma.sync.aligned.m16n8k8.row.col.f32.tf32.tf32.f32 "
        "{%0,%1,%2,%3},{%4,%5,%6,%7},{%8,%9},{%0,%1,%2,%3};\n"
        : "+f"(c[0]), "+f"(c[1]), "+f"(c[2]), "+f"(c[3])
        : "r"(a[0]), "r"(a[1]), "r"(a[2]), "r"(a[3]), "r"(b[0]), "r"(b[1]));
}

__device__ __forceinline__ void mma_bf16(float c[4], const uint32_t a[4], uint32_t b0, uint32_t b1) {
    asm volatile(
        "mma.sync.aligned.m16n8k16.row.col.f32.bf16.bf16.f32 "
        "{%0,%1,%2,%3},{%4,%5,%6,%7},{%8,%9},{%0,%1,%2,%3};\n"
        : "+f"(c[0]), "+f"(c[1]), "+f"(c[2]), "+f"(c[3])
        : "r"(a[0]), "r"(a[1]), "r"(a[2]), "r"(a[3]), "r"(b0), "r"(b1));
}

__device__ __forceinline__ uint32_t pack_bf16x2(float lo, float hi) {
    __nv_bfloat162 t = __floats2bfloat162_rn(lo, hi);
    return *reinterpret_cast<uint32_t*>(&t);
}

__device__ __forceinline__ void cp_async_16(void* smem, const void* gmem) {
    uint32_t s = (uint32_t)__cvta_generic_to_shared(smem);
    asm volatile("cp.async.cg.shared.global [%0], [%1], 16;\n" :: "r"(s), "l"(gmem) : "memory");
}
__device__ __forceinline__ void cp_commit() {
    asm volatile("cp.async.commit_group;\n" ::: "memory");
}
__device__ __forceinline__ void cp_wait1() {
    asm volatile("cp.async.wait_group 1;\n" ::: "memory");
}
__device__ __forceinline__ void cp_wait0() {
    asm volatile("cp.async.wait_group 0;\n" ::: "memory");
}

__device__ __forceinline__ void ldsm_x4(uint32_t& r0, uint32_t& r1, uint32_t& r2, uint32_t& r3, uint32_t addr) {
    asm volatile("ldmatrix.sync.aligned.m8n8.x4.shared.b16 {%0,%1,%2,%3}, [%4];"
                 : "=r"(r0), "=r"(r1), "=r"(r2), "=r"(r3) : "r"(addr));
}
__device__ __forceinline__ void ldsm_x4_t(uint32_t& r0, uint32_t& r1, uint32_t& r2, uint32_t& r3, uint32_t addr) {
    asm volatile("ldmatrix.sync.aligned.m8n8.x4.trans.shared.b16 {%0,%1,%2,%3}, [%4];"
                 : "=r"(r0), "=r"(r1), "=r"(r2), "=r"(r3) : "r"(addr));
}

// ------------------------- generic tf32 GEMM (cp.async 2-stage) -------------------------
// BM=128, BN=64, BK=16, 256 threads (8 warps). A stride 20, B stride 72.
// MODE 0: qkv -> scatter bf16 q/k/v head-major (q pre-scaled)
// MODE 1: + bias + residual(extra)    (out proj)
// MODE 2: + bias                      (xpart)
// MODE 3: + bias, relu                (ffn1)
// MODE 4: + bias + residual(extra)    (ffn2)
#define GEMM_LOAD_TILE(st, k0) do { \
    cp_async_16(&As[st][ar0 * 20 + ac0],        A + (size_t)(bm + ar0) * K + (k0) + ac0); \
    cp_async_16(&As[st][(ar0 + 64) * 20 + ac0], A + (size_t)(bm + ar0 + 64) * K + (k0) + ac0); \
    cp_async_16(&Bs[st][br * 72 + bc],          B + (size_t)((k0) + br) * Ncols + bn + bc); \
    cp_commit(); \
} while (0)

template <int MODE>
__global__ void __launch_bounds__(256)
gemm_tf32_kernel(const float* __restrict__ A, const float* __restrict__ B,
                 const float* __restrict__ bias, const float* __restrict__ extra,
                 float* __restrict__ Cout, int Ncols, int K) {
    __shared__ __align__(16) float As[2][128 * 20];
    __shared__ __align__(16) float Bs[2][16 * 72];

    const int bm = blockIdx.y * 128;
    const int bn = blockIdx.x * 64;
    const int tid = threadIdx.x;
    const int warp = tid >> 5;
    const int lane = tid & 31;
    const int g = lane >> 2;
    const int tg = lane & 3;
    const int wr = warp * 16;

    const int ar0 = tid >> 2, ac0 = (tid & 3) * 4;
    const int br = tid >> 4, bc = (tid & 15) * 4;

    float acc[8][4];
#pragma unroll
    for (int t = 0; t < 8; t++)
#pragma unroll
        for (int i = 0; i < 4; i++) acc[t][i] = 0.f;

    const int NT = K >> 4;
    GEMM_LOAD_TILE(0, 0);

    for (int it = 0; it < NT; it++) {
        const int st = it & 1;
        if (it + 1 < NT) {
            GEMM_LOAD_TILE(st ^ 1, (it + 1) << 4);
            cp_wait1();
        } else {
            cp_wait0();
        }
        __syncthreads();

        const float* Ap = &As[st][0];
        const float* Bp = &Bs[st][0];
#pragma unroll
        for (int s = 0; s < 2; s++) {
            uint32_t a[4];
            a[0] = cvt_tf32(Ap[(wr + g) * 20 + s * 8 + tg]);
            a[1] = cvt_tf32(Ap[(wr + g + 8) * 20 + s * 8 + tg]);
            a[2] = cvt_tf32(Ap[(wr + g) * 20 + s * 8 + tg + 4]);
            a[3] = cvt_tf32(Ap[(wr + g + 8) * 20 + s * 8 + tg + 4]);
#pragma unroll
            for (int t = 0; t < 8; t++) {
                uint32_t b[2];
                b[0] = cvt_tf32(Bp[(s * 8 + tg) * 72 + t * 8 + g]);
                b[1] = cvt_tf32(Bp[(s * 8 + tg + 4) * 72 + t * 8 + g]);
                mma_tf32(acc[t], a, b);
            }
        }
        __syncthreads();
    }

    // epilogue
#pragma unroll
    for (int t = 0; t < 8; t++) {
#pragma unroll
        for (int i = 0; i < 2; i++) {
            int row = bm + wr + g + i * 8;
#pragma unroll
            for (int j = 0; j < 2; j++) {
                int col = bn + t * 8 + tg * 2 + j;
                float v = acc[t][i * 2 + j];
                if (bias != nullptr) v += bias[col];
                if (MODE == 0) {
                    int part = col >> 8;
                    int head = (col & 255) >> 5;
                    int d = col & 31;
                    size_t idx = ((size_t)head * N_ATOMS + row) * HDIM + d;
                    if (part == 0)      g_q[idx] = __float2bfloat16(v * 0.17677669529663689f);
                    else if (part == 1) g_k[idx] = __float2bfloat16(v);
                    else                g_v[idx] = __float2bfloat16(v);
                } else if (MODE == 1 || MODE == 4) {
                    Cout[(size_t)row * Ncols + col] = v + extra[(size_t)row * Ncols + col];
                } else if (MODE == 2) {
                    Cout[(size_t)row * Ncols + col] = v;
                } else { // MODE 3
                    Cout[(size_t)row * Ncols + col] = fmaxf(v, 0.f);
                }
            }
        }
    }
}

// ------------------------- fused neighbor kernel -------------------------
// scores[row,:] = relu(neighbors[row,:] @ W + xpart[row/16,:]) @ w2 + b2
// BM=64, BN=256(full), BK=16, 512 threads (16 warps: 4 M-strips x 4 N-strips).
// g_h never materialized. Dynamic smem = 44032B (pipeline), reused as w2/xpart
// scratch in the epilogue; only sred (2KB) is static -> total 46080B < 48KB.
#define NF_LOAD(st, k0) do { \
    if (tid < 256) \
        cp_async_16(&As[(st) * 1280 + ar0 * 20 + ac0], A + (size_t)(bm + ar0) * HID + (k0) + ac0); \
    cp_async_16(&Bs[(st) * 4224 + br0 * 264 + bc0],       Bw + (size_t)((k0) + br0) * HID + bc0); \
    cp_async_16(&Bs[(st) * 4224 + (br0 + 8) * 264 + bc0], Bw + (size_t)((k0) + br0 + 8) * HID + bc0); \
    cp_commit(); \
} while (0)

__global__ void __launch_bounds__(512)
neigh_fused_kernel(const float* __restrict__ A /*neighbors*/, const float* __restrict__ Bw,
                   const float* __restrict__ xpart, const float* __restrict__ w2,
                   const float* __restrict__ b2) {
    extern __shared__ __align__(16) float dyn[];
    float* As = dyn;            // [2][64*20]   (mainloop)
    float* Bs = dyn + 2 * 1280; // [2][16*264]  (mainloop)
    __shared__ float sred[64 * NHEAD];

    const int bm = blockIdx.x * 64;
    const int tid = threadIdx.x;
    const int warp = tid >> 5;
    const int lane = tid & 31;
    const int g = lane >> 2;
    const int tg = lane & 3;
    const int wm = warp & 3;
    const int wn = warp >> 2;
    const int wr = wm * 16;
    const int cb = wn * 64;

    const int ar0 = tid >> 2, ac0 = (tid & 3) * 4;
    const int br0 = tid >> 6, bc0 = (tid & 63) * 4;

    if (tid < 64 * NHEAD) sred[tid] = 0.f;

    float acc[8][4];
#pragma unroll
    for (int t = 0; t < 8; t++)
#pragma unroll
        for (int i = 0; i < 4; i++) acc[t][i] = 0.f;

    NF_LOAD(0, 0);
    for (int it = 0; it < 16; it++) {
        const int st = it & 1;
        if (it + 1 < 16) {
            NF_LOAD(st ^ 1, (it + 1) << 4);
            cp_wait1();
        } else {
            cp_wait0();
        }
        __syncthreads();

        const float* Ap = As + st * 1280;
        const float* Bp = Bs + st * 4224;
#pragma unroll
        for (int s = 0; s < 2; s++) {
            uint32_t a[4];
            a[0] = cvt_tf32(Ap[(wr + g) * 20 + s * 8 + tg]);
            a[1] = cvt_tf32(Ap[(wr + g + 8) * 20 + s * 8 + tg]);
            a[2] = cvt_tf32(Ap[(wr + g) * 20 + s * 8 + tg + 4]);
            a[3] = cvt_tf32(Ap[(wr + g + 8) * 20 + s * 8 + tg + 4]);
#pragma unroll
            for (int t = 0; t < 8; t++) {
                uint32_t b[2];
                b[0] = cvt_tf32(Bp[(s * 8 + tg) * 264 + cb + t * 8 + g]);
                b[1] = cvt_tf32(Bp[(s * 8 + tg + 4) * 264 + cb + t * 8 + g]);
                mma_tf32(acc[t], a, b);
            }
        }
        __syncthreads();
    }

    // pipeline buffers are dead now — reuse dyn as epilogue scratch
    float* w2s = dyn;          // [HID*NHEAD] = 2048 floats
    float* xps = dyn + 2048;   // [4*HID]     = 1024 floats
    for (int i = tid; i < HID * NHEAD; i += 512) w2s[i] = w2[i];
    for (int i = tid; i < 4 * HID; i += 512) xps[i] = xpart[(size_t)(bm >> 4) * HID + i];
    __syncthreads();

    // epilogue: h = relu(acc + xpart), partial scores = h @ w2
    float part[2][NHEAD];
#pragma unroll
    for (int i = 0; i < 2; i++)
#pragma unroll
        for (int j = 0; j < NHEAD; j++) part[i][j] = 0.f;

#pragma unroll
    for (int t = 0; t < 8; t++) {
#pragma unroll
        for (int j2 = 0; j2 < 2; j2++) {
            int col = cb + t * 8 + tg * 2 + j2;
#pragma unroll
            for (int i = 0; i < 2; i++) {
                float h = fmaxf(acc[t][i * 2 + j2] + xps[wm * HID + col], 0.f);
#pragma unroll
                for (int j = 0; j < NHEAD; j++)
                    part[i][j] += h * w2s[col * NHEAD + j];
            }
        }
    }
#pragma unroll
    for (int i = 0; i < 2; i++)
#pragma unroll
        for (int j = 0; j < NHEAD; j++) {
            part[i][j] += __shfl_xor_sync(0xffffffffu, part[i][j], 1);
            part[i][j] += __shfl_xor_sync(0xffffffffu, part[i][j], 2);
        }
    if (tg == 0) {
#pragma unroll
        for (int i = 0; i < 2; i++) {
            int rl = wr + g + i * 8;
#pragma unroll
            for (int j = 0; j < NHEAD; j++)
                atomicAdd(&sred[rl * NHEAD + j], part[i][j]);
        }
    }
    __syncthreads();
    if (tid < 64 * NHEAD)
        g_scores[(size_t)(bm + (tid >> 3)) * NHEAD + (tid & 7)] = sred[tid] + b2[tid & 7];
}

// ------------------------- flash attention (ldmatrix + cp.async) -------------------------
#define KV_STRIDE 40  // halves per row: 32 data + 8 pad

#define ATTN_LOAD(st, kt) do { \
    cp_async_16(&Ks[st][r0 * KV_STRIDE + p0],        Kg + (size_t)((kt) + r0) * HDIM + p0); \
    cp_async_16(&Ks[st][(r0 + 32) * KV_STRIDE + p0], Kg + (size_t)((kt) + r0 + 32) * HDIM + p0); \
    cp_async_16(&Vs[st][r0 * KV_STRIDE + p0],        Vg + (size_t)((kt) + r0) * HDIM + p0); \
    cp_async_16(&Vs[st][(r0 + 32) * KV_STRIDE + p0], Vg + (size_t)((kt) + r0 + 32) * HDIM + p0); \
    cp_commit(); \
} while (0)

__global__ void __launch_bounds__(128)
flash_attn_kernel() {
    __shared__ __align__(16) __nv_bfloat16 Ks[2][64 * KV_STRIDE];
    __shared__ __align__(16) __nv_bfloat16 Vs[2][64 * KV_STRIDE];

    const int h = blockIdx.y;
    const int qt = blockIdx.x;
    const int tid = threadIdx.x;
    const int warp = tid >> 5;
    const int lane = tid & 31;
    const int g = lane >> 2;
    const int tg = lane & 3;
    const int i8 = lane & 7;
    const int mq = lane >> 3;

    const int r0 = tid >> 2, p0 = (tid & 3) * 8;
    const int qrow = qt * 64 + warp * 16;

    const __nv_bfloat16* Kg = g_k + (size_t)h * N_ATOMS * HDIM;
    const __nv_bfloat16* Vg = g_v + (size_t)h * N_ATOMS * HDIM;

    const uint32_t ksb = (uint32_t)__cvta_generic_to_shared(&Ks[0][0]);
    const uint32_t vsb = (uint32_t)__cvta_generic_to_shared(&Vs[0][0]);

    // Q fragments
    const uint32_t* qbase = reinterpret_cast<const uint32_t*>(g_q + (size_t)h * N_ATOMS * HDIM);
    uint32_t qf[2][4];
#pragma unroll
    for (int s = 0; s < 2; s++) {
        qf[s][0] = qbase[(qrow + g) * 16 + s * 8 + tg];
        qf[s][1] = qbase[(qrow + g + 8) * 16 + s * 8 + tg];
        qf[s][2] = qbase[(qrow + g) * 16 + s * 8 + tg + 4];
        qf[s][3] = qbase[(qrow + g + 8) * 16 + s * 8 + tg + 4];
    }

    float o[4][4];
#pragma unroll
    for (int t = 0; t < 4; t++)
#pragma unroll
        for (int i = 0; i < 4; i++) o[t][i] = 0.f;
    float m0 = -1e30f, m1 = -1e30f, l0 = 0.f, l1 = 0.f;

    ATTN_LOAD(0, 0);
    const int NIT = N_ATOMS / 64;
    for (int it = 0; it < NIT; it++) {
        const int st = it & 1;
        if (it + 1 < NIT) {
            ATTN_LOAD(st ^ 1, (it + 1) * 64);
            cp_wait1();
        } else {
            cp_wait0();
        }
        __syncthreads();

        const uint32_t kst = ksb + st * (64 * KV_STRIDE * 2);
        const uint32_t vst = vsb + st * (64 * KV_STRIDE * 2);

        // S = Q @ K^T (16 x 64)
        float s[8][4];
#pragma unroll
        for (int t = 0; t < 8; t++)
#pragma unroll
            for (int i = 0; i < 4; i++) s[t][i] = 0.f;
#pragma unroll
        for (int t = 0; t < 8; t++) {
            uint32_t b0, b1, b2, b3;
            uint32_t addr = kst + ((t * 8 + i8) * KV_STRIDE + mq * 8) * 2;
            ldsm_x4(b0, b1, b2, b3, addr);
            mma_bf16(s[t], qf[0], b0, b1);
            mma_bf16(s[t], qf[1], b2, b3);
        }

        // online softmax
        float mt0 = -1e30f, mt1 = -1e30f;
#pragma unroll
        for (int t = 0; t < 8; t++) {
            mt0 = fmaxf(mt0, fmaxf(s[t][0], s[t][1]));
            mt1 = fmaxf(mt1, fmaxf(s[t][2], s[t][3]));
        }
        mt0 = fmaxf(mt0, __shfl_xor_sync(0xffffffffu, mt0, 1));
        mt0 = fmaxf(mt0, __shfl_xor_sync(0xffffffffu, mt0, 2));
        mt1 = fmaxf(mt1, __shfl_xor_sync(0xffffffffu, mt1, 1));
        mt1 = fmaxf(mt1, __shfl_xor_sync(0xffffffffu, mt1, 2));

        float mn0 = fmaxf(m0, mt0), mn1 = fmaxf(m1, mt1);
        float sc0 = __expf(m0 - mn0), sc1 = __expf(m1 - mn1);

        float rs0 = 0.f, rs1 = 0.f;
        uint32_t p[4][4];
#pragma unroll
        for (int t2 = 0; t2 < 4; t2++) {
            float e00 = __expf(s[2 * t2][0] - mn0);
            float e01 = __expf(s[2 * t2][1] - mn0);
            float e02 = __expf(s[2 * t2][2] - mn1);
            float e03 = __expf(s[2 * t2][3] - mn1);
            float e10 = __expf(s[2 * t2 + 1][0] - mn0);
            float e11 = __expf(s[2 * t2 + 1][1] - mn0);
            float e12 = __expf(s[2 * t2 + 1][2] - mn1);
            float e13 = __expf(s[2 * t2 + 1][3] - mn1);
            rs0 += e00 + e01 + e10 + e11;
            rs1 += e02 + e03 + e12 + e13;
            p[t2][0] = pack_bf16x2(e00, e01);
            p[t2][1] = pack_bf16x2(e02, e03);
            p[t2][2] = pack_bf16x2(e10, e11);
            p[t2][3] = pack_bf16x2(e12, e13);
        }
        rs0 += __shfl_xor_sync(0xffffffffu, rs0, 1);
        rs0 += __shfl_xor_sync(0xffffffffu, rs0, 2);
        rs1 += __shfl_xor_sync(0xffffffffu, rs1, 1);
        rs1 += __shfl_xor_sync(0xffffffffu, rs1, 2);

        l0 = l0 * sc0 + rs0;
        l1 = l1 * sc1 + rs1;
        m0 = mn0;
        m1 = mn1;
#pragma unroll
        for (int t = 0; t < 4; t++) {
            o[t][0] *= sc0; o[t][1] *= sc0;
            o[t][2] *= sc1; o[t][3] *= sc1;
        }

        // O += P @ V
#pragma unroll
        for (int k2 = 0; k2 < 4; k2++) {
#pragma unroll
            for (int tp = 0; tp < 2; tp++) {
                uint32_t b0, b1, b2, b3;
                uint32_t addr = vst +
                    ((k2 * 16 + (mq & 1) * 8 + i8) * KV_STRIDE + (tp * 2 + (mq >> 1)) * 8) * 2;
                ldsm_x4_t(b0, b1, b2, b3, addr);
                mma_bf16(o[tp * 2], p[k2], b0, b1);
                mma_bf16(o[tp * 2 + 1], p[k2], b2, b3);
            }
        }
        __syncthreads();
    }

    const float il0 = 1.f / l0, il1 = 1.f / l1;
    const int ro0 = qrow + g, ro1 = qrow + g + 8;
#pragma unroll
    for (int t = 0; t < 4; t++) {
        int col = h * HDIM + t * 8 + tg * 2;
        g_attno[(size_t)ro0 * HID + col]     = o[t][0] * il0;
        g_attno[(size_t)ro0 * HID + col + 1] = o[t][1] * il0;
        g_attno[(size_t)ro1 * HID + col]     = o[t][2] * il1;
        g_attno[(size_t)ro1 * HID + col + 1] = o[t][3] * il1;
    }
}

// ------------------------- layer norm -------------------------
__global__ void __launch_bounds__(128)
ln_kernel(const float* __restrict__ in, const float* __restrict__ scale,
          const float* __restrict__ bias, float* __restrict__ out) {
    const int warp = threadIdx.x >> 5;
    const int lane = threadIdx.x & 31;
    const int row = blockIdx.x * 4 + warp;
    const float* r = in + (size_t)row * HID;

    float v[8];
#pragma unroll
    for (int i = 0; i < 8; i++) v[i] = r[lane + i * 32];

    float s = 0.f;
#pragma unroll
    for (int i = 0; i < 8; i++) s += v[i];
#pragma unroll
    for (int o = 16; o > 0; o >>= 1) s += __shfl_xor_sync(0xffffffffu, s, o);
    const float mu = s * (1.f / HID);

    float q = 0.f;
#pragma unroll
    for (int i = 0; i < 8; i++) {
        float d = v[i] - mu;
        q += d * d;
    }
#pragma unroll
    for (int o = 16; o > 0; o >>= 1) q += __shfl_xor_sync(0xffffffffu, q, o);
    const float inv = rsqrtf(q * (1.f / HID) + 1e-5f);

#pragma unroll
    for (int i = 0; i < 8; i++) {
        int c = lane + i * 32;
        out[(size_t)row * HID + c] = (v[i] - mu) * inv * scale[c] + bias[c];
    }
}

// ------------------------- neighbor softmax + message + residual -------------------------
__global__ void __launch_bounds__(256)
neighbor_msg_kernel(const float* __restrict__ neighbors, const float* __restrict__ edge) {
    const int n = blockIdx.x;
    const int tid = threadIdx.x;

    __shared__ float sc[M_BONDS][NHEAD];
    __shared__ float wn[M_BONDS][NHEAD];
    __shared__ float w[M_BONDS];

    if (tid < M_BONDS * NHEAD)
        sc[tid >> 3][tid & 7] = g_scores[(size_t)n * (M_BONDS * NHEAD) + tid];
    __syncthreads();

    if (tid < NHEAD) {
        float mx = -1e30f;
        for (int m = 0; m < M_BONDS; m++) mx = fmaxf(mx, sc[m][tid]);
        float s = 0.f;
        for (int m = 0; m < M_BONDS; m++) {
            float e = __expf(sc[m][tid] - mx);
            wn[m][tid] = e;
            s += e;
        }
        float inv = 1.f / s;
        for (int m = 0; m < M_BONDS; m++) wn[m][tid] *= inv;
    }
    __syncthreads();
    if (tid < M_BONDS) {
        float s = 0.f;
        for (int j = 0; j < NHEAD; j++) s += wn[tid][j];
        w[tid] = s * (1.f / NHEAD);
    }
    __syncthreads();

    const int d = tid;
    const size_t base = ((size_t)n * M_BONDS) * HID + d;
    float msg = 0.f;
#pragma unroll
    for (int m = 0; m < M_BONDS; m++)
        msg += neighbors[base + (size_t)m * HID] * edge[base + (size_t)m * HID] * w[m];
    g_x2[(size_t)n * HID + d] = g_x1[(size_t)n * HID + d] + msg;
}

// ------------------------- launch -------------------------
extern "C" void kernel_launch(void* const* d_in, const int* in_sizes, int n_in,
                              void* d_out, int out_size) {
    const float* x          = (const float*)d_in[0];
    const float* neighbors  = (const float*)d_in[1];
    const float* edge       = (const float*)d_in[2];
    const float* in_proj_w  = (const float*)d_in[3];
    const float* in_proj_b  = (const float*)d_in[4];
    const float* out_proj_w = (const float*)d_in[5];
    const float* out_proj_b = (const float*)d_in[6];
    const float* ln1_s      = (const float*)d_in[7];
    const float* ln1_b      = (const float*)d_in[8];
    const float* na_w1      = (const float*)d_in[9];
    const float* na_b1      = (const float*)d_in[10];
    const float* na_w2      = (const float*)d_in[11];
    const float* na_b2      = (const float*)d_in[12];
    const float* ff_w1      = (const float*)d_in[13];
    const float* ff_b1      = (const float*)d_in[14];
    const float* ff_w2      = (const float*)d_in[15];
    const float* ff_b2      = (const float*)d_in[16];
    const float* ln2_s      = (const float*)d_in[17];
    const float* ln2_b      = (const float*)d_in[18];
    float* out = (float*)d_out;

    float *attno, *tmp, *x1, *xpart, *x2, *ff;
    cudaGetSymbolAddress((void**)&attno, g_attno);
    cudaGetSymbolAddress((void**)&tmp,   g_tmp);
    cudaGetSymbolAddress((void**)&x1,    g_x1);
    cudaGetSymbolAddress((void**)&xpart, g_xpart);
    cudaGetSymbolAddress((void**)&x2,    g_x2);
    cudaGetSymbolAddress((void**)&ff,    g_ff);

    // 1. qkv projection -> bf16 q/k/v head-major (q pre-scaled)
    gemm_tf32_kernel<0><<<dim3(12, 64), 256>>>(x, in_proj_w, in_proj_b, nullptr, nullptr, 768, HID);

    // 2. flash attention -> g_attno
    flash_attn_kernel<<<dim3(N_ATOMS / 64, NHEAD), 128>>>();

    // 3. out-proj + residual -> g_tmp
    gemm_tf32_kernel<1><<<dim3(4, 64), 256>>>(attno, out_proj_w, out_proj_b, x, tmp, HID, HID);

    // 4. LN1 -> g_x1
    ln_kernel<<<N_ATOMS / 4, 128>>>(tmp, ln1_s, ln1_b, x1);

    // 5. x-part of neighbor MLP -> g_xpart
    gemm_tf32_kernel<2><<<dim3(4, 64), 256>>>(x1, na_w1, na_b1, nullptr, xpart, HID, HID);

    // 6. fused neighbor GEMM + relu + scores -> g_scores (no g_h)
    neigh_fused_kernel<<<(N_ATOMS * M_BONDS) / 64, 512, 44032>>>(
        neighbors, na_w1 + 256 * HID, xpart, na_w2, na_b2);

    // 7. softmax over bonds + message + residual -> g_x2
    neighbor_msg_kernel<<<N_ATOMS, 256>>>(neighbors, edge);

    // 8. FFN layer 1 -> g_ff
    gemm_tf32_kernel<3><<<dim3(16, 64), 256>>>(x2, ff_w1, ff_b1, nullptr, ff, 4 * HID, HID);

    // 9. FFN layer 2 + residual -> g_tmp
    gemm_tf32_kernel<4><<<dim3(4, 64), 256>>>(ff, ff_w2, ff_b2, x2, tmp, HID, 4 * HID);

    // 10. LN2 -> out
    ln_kernel<<<N_ATOMS / 4, 128>>>(tmp, ln2_s, ln2_b, out);
}